// round 9
// baseline (speedup 1.0000x reference)
#include <cuda_runtime.h>
#include <cstdint>

#define NN 512000       // nodes = 512 * 1000
#define NE 8192000      // edges per branch
#define NB 512          // batch
#define NS 1000         // stations
#define NH 64           // ff hidden
#define NA 1024         // actions
#define EPSF 1e-5f

#define TB 256
#define STATS_BLKS 1024
#define BINS 256                // dst bins
#define NPB 2000                // nodes per bin (256*2000 = NN)
#define BCAP 33536              // per-bin capacity (mean 32000, +8.6 sigma)
#define BIN_CTAS 4000           // 4000 * 2048 = NE
#define KT 40                   // ff1 k-tile

// ---------------- scratch ----------------------------------------------------
__device__ float    g_stats[3][16];            // per branch: sum[8], sumsq[8]
__device__ unsigned g_bcnt[3][BINS];           // bin fill counters
__device__ unsigned g_binned[3][BINS * BCAP];  // packed edges: src<<11 | dst_local
__device__ unsigned g_deg[3][NN];              // in-degree (no self loop)
__device__ float4   g_z1[3][NN];               // xw * dinv
__device__ float4   g_acc1[3][NN];             // conv1 acc (init = self loop)
__device__ float    g_z2[3][NN];
__device__ float    g_acc2[3][NN];
__device__ float    g_hidpart[NB * NH];        // ff1 k-split partials

// ---------------- kernels ----------------------------------------------------

__global__ void zeroK() {
    int i = blockIdx.x * blockDim.x + threadIdx.x;
    if (i < 3 * BINS)   ((unsigned*)g_bcnt)[i] = 0u;
    if (i < 48)         ((float*)g_stats)[i] = 0.f;
    if (i < NB * NH)    g_hidpart[i] = 0.f;
}

// per-branch feature stats (sum, sumsq per feature)
__global__ void statsK(const float* __restrict__ x0, const float* __restrict__ x1,
                       const float* __restrict__ x2) {
    int br = blockIdx.y;
    const float* x = br == 0 ? x0 : (br == 1 ? x1 : x2);
    float s[8], q[8];
#pragma unroll
    for (int i = 0; i < 8; i++) { s[i] = 0.f; q[i] = 0.f; }
    int stride = STATS_BLKS * TB;
    for (int n = blockIdx.x * TB + threadIdx.x; n < NN; n += stride) {
        const float4* p = (const float4*)(x + (size_t)n * 8);
        float4 a = __ldg(p), b = __ldg(p + 1);
        float v[8] = {a.x, a.y, a.z, a.w, b.x, b.y, b.z, b.w};
#pragma unroll
        for (int i = 0; i < 8; i++) { s[i] += v[i]; q[i] += v[i] * v[i]; }
    }
#pragma unroll
    for (int i = 0; i < 8; i++) {
#pragma unroll
        for (int o = 16; o; o >>= 1) {
            s[i] += __shfl_down_sync(0xffffffffu, s[i], o);
            q[i] += __shfl_down_sync(0xffffffffu, q[i], o);
        }
    }
    __shared__ float sh[16];
    if (threadIdx.x < 16) sh[threadIdx.x] = 0.f;
    __syncthreads();
    if ((threadIdx.x & 31) == 0) {
#pragma unroll
        for (int i = 0; i < 8; i++) {
            atomicAdd(&sh[i], s[i]);
            atomicAdd(&sh[8 + i], q[i]);
        }
    }
    __syncthreads();
    if (threadIdx.x < 16) atomicAdd(&g_stats[br][threadIdx.x], sh[threadIdx.x]);
}

// bin edges by dst: per-CTA smem histogram -> global reservation -> scattered
// packed writes. 2048 edges per CTA, 8 per thread.
__global__ void binK(const int* __restrict__ e0, const int* __restrict__ e1,
                     const int* __restrict__ e2) {
    int br = blockIdx.y;
    const int* ei = br == 0 ? e0 : (br == 1 ? e1 : e2);
    __shared__ unsigned hist[BINS], gbase[BINS], cur[BINS];
    int tid = threadIdx.x;
    int base = blockIdx.x * 2048 + tid * 8;
    int4 sa = __ldg((const int4*)(ei + base));
    int4 sb = __ldg((const int4*)(ei + base + 4));
    int4 da = __ldg((const int4*)(ei + NE + base));
    int4 db = __ldg((const int4*)(ei + NE + base + 4));
    int ss[8] = {sa.x, sa.y, sa.z, sa.w, sb.x, sb.y, sb.z, sb.w};
    int ds[8] = {da.x, da.y, da.z, da.w, db.x, db.y, db.z, db.w};
    int bn[8];
    unsigned pk[8];
#pragma unroll
    for (int k = 0; k < 8; k++) {
        bn[k] = ds[k] / NPB;
        int dl = ds[k] - bn[k] * NPB;
        pk[k] = ((unsigned)ss[k] << 11) | (unsigned)dl;
    }
    hist[tid] = 0u;
    __syncthreads();
#pragma unroll
    for (int k = 0; k < 8; k++) atomicAdd(&hist[bn[k]], 1u);
    __syncthreads();
    gbase[tid] = atomicAdd(&g_bcnt[br][tid], hist[tid]);
    cur[tid] = 0u;
    __syncthreads();
#pragma unroll
    for (int k = 0; k < 8; k++) {
        unsigned off = atomicAdd(&cur[bn[k]], 1u);
        unsigned pos = gbase[bn[k]] + off;
        if (pos < BCAP)
            g_binned[br][(size_t)bn[k] * BCAP + pos] = pk[k];
    }
}

// deg consumer: one CTA per (bin, branch); smem histogram, coalesced IO.
__global__ void degC() {
    int br = blockIdx.y, bin = blockIdx.x, tid = threadIdx.x;
    __shared__ unsigned dc[NPB];
    for (int i = tid; i < NPB; i += TB) dc[i] = 0u;
    __syncthreads();
    int cnt = min(g_bcnt[br][bin], (unsigned)BCAP);
    const unsigned* bp = g_binned[br] + (size_t)bin * BCAP;
    int full = (cnt / (TB * 4)) * (TB * 4);
    for (int b0 = 0; b0 < full; b0 += TB * 4) {
        uint4 p = __ldg((const uint4*)(bp + b0 + tid * 4));
        atomicAdd(&dc[p.x & 2047u], 1u);
        atomicAdd(&dc[p.y & 2047u], 1u);
        atomicAdd(&dc[p.z & 2047u], 1u);
        atomicAdd(&dc[p.w & 2047u], 1u);
    }
    for (int i = full + tid; i < cnt; i += TB)
        atomicAdd(&dc[__ldg(bp + i) & 2047u], 1u);
    __syncthreads();
    unsigned* dp = &g_deg[br][bin * NPB];
    for (int i = tid; i < NPB; i += TB) dp[i] = dc[i];
}

// z1 = (norm(x)@W1)*dinv, GraphNorm affine folded in (thread 0 per block).
__global__ void z1K(const float* __restrict__ x0, const float* __restrict__ x1,
                    const float* __restrict__ x2,
                    const float* __restrict__ nw, const float* __restrict__ nbp,
                    const float* __restrict__ nms, const float* __restrict__ W1) {
    int br = blockIdx.y;
    const float* x = br == 0 ? x0 : (br == 1 ? x1 : x2);
    __shared__ float sA[32];
    __shared__ float sD[4];
    if (threadIdx.x == 0) {
        const float inv = 1.0f / (float)NN;
        float a[8], d[8];
#pragma unroll
        for (int i = 0; i < 8; i++) {
            float mean = g_stats[br][i] * inv;
            float m2   = g_stats[br][8 + i] * inv;
            float c    = mean * nms[i];
            float var  = m2 - 2.f * c * mean + c * c;
            float ai   = nw[i] * rsqrtf(var + EPSF);
            a[i] = ai;
            d[i] = nbp[i] - c * ai;
        }
#pragma unroll
        for (int j = 0; j < 4; j++) {
            float dv = 0.f;
#pragma unroll
            for (int i = 0; i < 8; i++) {
                sA[i * 4 + j] = a[i] * W1[i * 4 + j];
                dv += d[i] * W1[i * 4 + j];
            }
            sD[j] = dv;
        }
    }
    __syncthreads();
    int n = blockIdx.x * TB + threadIdx.x;
    if (n >= NN) return;
    const float4* p = (const float4*)(x + (size_t)n * 8);
    float4 a = __ldg(p), b = __ldg(p + 1);
    float v[8] = {a.x, a.y, a.z, a.w, b.x, b.y, b.z, b.w};
    float dinv = rsqrtf((float)(g_deg[br][n] + 1u));
    float o[4];
#pragma unroll
    for (int j = 0; j < 4; j++) {
        float acc = sD[j];
#pragma unroll
        for (int i = 0; i < 8; i++) acc += v[i] * sA[i * 4 + j];
        o[j] = acc * dinv;
    }
    float4 z = make_float4(o[0], o[1], o[2], o[3]);
    g_z1[br][n]  = z;
    g_acc1[br][n] = z;
}

// conv1 consumer: one CTA per (bin, branch). Gather z1[src] (L2), accumulate
// in smem (SoA, conflict-free banks), coalesced flush into g_acc1.
__global__ void conv1C() {
    int br = blockIdx.y, bin = blockIdx.x, tid = threadIdx.x;
    __shared__ float a0[NPB], a1[NPB], a2[NPB], a3[NPB];
    for (int i = tid; i < NPB; i += TB) { a0[i] = 0.f; a1[i] = 0.f; a2[i] = 0.f; a3[i] = 0.f; }
    __syncthreads();
    int cnt = min(g_bcnt[br][bin], (unsigned)BCAP);
    const unsigned* bp = g_binned[br] + (size_t)bin * BCAP;
    int full = (cnt / (TB * 4)) * (TB * 4);
    for (int b0 = 0; b0 < full; b0 += TB * 4) {
        uint4 p = __ldg((const uint4*)(bp + b0 + tid * 4));
        float4 z0 = __ldg(&g_z1[br][p.x >> 11]);
        float4 z1 = __ldg(&g_z1[br][p.y >> 11]);
        float4 z2 = __ldg(&g_z1[br][p.z >> 11]);
        float4 z3 = __ldg(&g_z1[br][p.w >> 11]);
        int d0 = p.x & 2047, d1 = p.y & 2047, d2 = p.z & 2047, d3 = p.w & 2047;
        atomicAdd(&a0[d0], z0.x); atomicAdd(&a1[d0], z0.y);
        atomicAdd(&a2[d0], z0.z); atomicAdd(&a3[d0], z0.w);
        atomicAdd(&a0[d1], z1.x); atomicAdd(&a1[d1], z1.y);
        atomicAdd(&a2[d1], z1.z); atomicAdd(&a3[d1], z1.w);
        atomicAdd(&a0[d2], z2.x); atomicAdd(&a1[d2], z2.y);
        atomicAdd(&a2[d2], z2.z); atomicAdd(&a3[d2], z2.w);
        atomicAdd(&a0[d3], z3.x); atomicAdd(&a1[d3], z3.y);
        atomicAdd(&a2[d3], z3.z); atomicAdd(&a3[d3], z3.w);
    }
    for (int i = full + tid; i < cnt; i += TB) {
        unsigned p = __ldg(bp + i);
        float4 z = __ldg(&g_z1[br][p >> 11]);
        int d = p & 2047;
        atomicAdd(&a0[d], z.x); atomicAdd(&a1[d], z.y);
        atomicAdd(&a2[d], z.z); atomicAdd(&a3[d], z.w);
    }
    __syncthreads();
    float4* ap = &g_acc1[br][bin * NPB];
    for (int i = tid; i < NPB; i += TB) {
        float4 v = ap[i];
        v.x += a0[i]; v.y += a1[i]; v.z += a2[i]; v.w += a3[i];
        ap[i] = v;
    }
}

// h1 = relu(dinv*acc1 + b1); z2 = (h1 . w2) * dinv; acc2 init = z2
__global__ void h1z2K(const float* __restrict__ b1, const float* __restrict__ w2) {
    int br = blockIdx.y;
    int n = blockIdx.x * TB + threadIdx.x;
    if (n >= NN) return;
    float dinv = rsqrtf((float)(g_deg[br][n] + 1u));
    float4 acc = g_acc1[br][n];
    float h0 = fmaxf(fmaf(dinv, acc.x, b1[0]), 0.f);
    float h1 = fmaxf(fmaf(dinv, acc.y, b1[1]), 0.f);
    float h2 = fmaxf(fmaf(dinv, acc.z, b1[2]), 0.f);
    float h3 = fmaxf(fmaf(dinv, acc.w, b1[3]), 0.f);
    float z2 = (h0 * w2[0] + h1 * w2[1] + h2 * w2[2] + h3 * w2[3]) * dinv;
    g_z2[br][n]  = z2;
    g_acc2[br][n] = z2;
}

// conv2 consumer: gather z2[src], smem accumulate, flush into g_acc2.
__global__ void conv2C() {
    int br = blockIdx.y, bin = blockIdx.x, tid = threadIdx.x;
    __shared__ float acc[NPB];
    for (int i = tid; i < NPB; i += TB) acc[i] = 0.f;
    __syncthreads();
    int cnt = min(g_bcnt[br][bin], (unsigned)BCAP);
    const unsigned* bp = g_binned[br] + (size_t)bin * BCAP;
    int full = (cnt / (TB * 4)) * (TB * 4);
    for (int b0 = 0; b0 < full; b0 += TB * 4) {
        uint4 p = __ldg((const uint4*)(bp + b0 + tid * 4));
        float v0 = __ldg(&g_z2[br][p.x >> 11]);
        float v1 = __ldg(&g_z2[br][p.y >> 11]);
        float v2 = __ldg(&g_z2[br][p.z >> 11]);
        float v3 = __ldg(&g_z2[br][p.w >> 11]);
        atomicAdd(&acc[p.x & 2047u], v0);
        atomicAdd(&acc[p.y & 2047u], v1);
        atomicAdd(&acc[p.z & 2047u], v2);
        atomicAdd(&acc[p.w & 2047u], v3);
    }
    for (int i = full + tid; i < cnt; i += TB) {
        unsigned p = __ldg(bp + i);
        atomicAdd(&acc[p & 2047u], __ldg(&g_z2[br][p >> 11]));
    }
    __syncthreads();
    float* ap = &g_acc2[br][bin * NPB];
    for (int i = tid; i < NPB; i += TB) ap[i] += acc[i];
}

// ff1 tiled GEMM with fused conv2 epilogue in the A-tile load.
__global__ void ff1K(const float* __restrict__ b2, const float* __restrict__ w1f) {
    __shared__ float As[KT][65];
    __shared__ float Bs[KT][64];
    int b0 = blockIdx.x * 64;
    int kbase = blockIdx.y * 600;
    float b2v = __ldg(b2);
    int tid = threadIdx.x;
    int tr = tid >> 4;
    int tc = tid & 15;
    float C[4][4];
#pragma unroll
    for (int i = 0; i < 4; i++)
#pragma unroll
        for (int j = 0; j < 4; j++) C[i][j] = 0.f;

    for (int t = 0; t < 600 / KT; t++) {
        int k0 = kbase + t * KT;
        int br = k0 / NS;
        int s0 = k0 - br * NS;
        for (int e = tid; e < (KT / 4) * 64; e += TB) {
            int kk4 = (e >> 6) << 2;
            int r   = e & 63;
            int n   = (b0 + r) * NS + s0 + kk4;
            float4 av = *(const float4*)&g_acc2[br][n];
            uint4  dv = *(const uint4*)&g_deg[br][n];
            As[kk4 + 0][r] = fmaxf(fmaf(rsqrtf((float)(dv.x + 1u)), av.x, b2v), 0.f);
            As[kk4 + 1][r] = fmaxf(fmaf(rsqrtf((float)(dv.y + 1u)), av.y, b2v), 0.f);
            As[kk4 + 2][r] = fmaxf(fmaf(rsqrtf((float)(dv.z + 1u)), av.z, b2v), 0.f);
            As[kk4 + 3][r] = fmaxf(fmaf(rsqrtf((float)(dv.w + 1u)), av.w, b2v), 0.f);
        }
        for (int e = tid; e < KT * 16; e += TB) {
            int kk = e >> 4;
            int c4 = (e & 15) * 4;
            float4 wv = __ldg((const float4*)(w1f + (size_t)(k0 + kk) * NH + c4));
            Bs[kk][c4 + 0] = wv.x;
            Bs[kk][c4 + 1] = wv.y;
            Bs[kk][c4 + 2] = wv.z;
            Bs[kk][c4 + 3] = wv.w;
        }
        __syncthreads();
#pragma unroll 8
        for (int kk = 0; kk < KT; kk++) {
            float a[4], b[4];
#pragma unroll
            for (int i = 0; i < 4; i++) a[i] = As[kk][tr + 16 * i];
#pragma unroll
            for (int j = 0; j < 4; j++) b[j] = Bs[kk][tc + 16 * j];
#pragma unroll
            for (int i = 0; i < 4; i++)
#pragma unroll
                for (int j = 0; j < 4; j++) C[i][j] += a[i] * b[j];
        }
        __syncthreads();
    }
#pragma unroll
    for (int i = 0; i < 4; i++)
#pragma unroll
        for (int j = 0; j < 4; j++)
            atomicAdd(&g_hidpart[(b0 + tr + 16 * i) * NH + tc + 16 * j], C[i][j]);
}

// ff2 tiled GEMM: relu(hidpart + b1f) @ w2f + b2f, * mask
__global__ void ff2K(const float* __restrict__ b1f, const float* __restrict__ w2f,
                     const float* __restrict__ b2f, const float* __restrict__ mask,
                     float* __restrict__ out) {
    __shared__ float As2[NH][65];
    __shared__ float Bs2[NH][64];
    int r0 = blockIdx.x * 64;
    int c0 = blockIdx.y * 64;
    int tid = threadIdx.x;
    for (int e = tid; e < NH * 64; e += TB) {
        int k = e >> 6;
        int r = e & 63;
        As2[k][r] = fmaxf(g_hidpart[(r0 + r) * NH + k] + __ldg(b1f + k), 0.f);
    }
    for (int e = tid; e < NH * 16; e += TB) {
        int k  = e >> 4;
        int c4 = (e & 15) * 4;
        float4 wv = __ldg((const float4*)(w2f + (size_t)k * NA + c0 + c4));
        Bs2[k][c4 + 0] = wv.x;
        Bs2[k][c4 + 1] = wv.y;
        Bs2[k][c4 + 2] = wv.z;
        Bs2[k][c4 + 3] = wv.w;
    }
    __syncthreads();
    int tr = tid >> 4;
    int tc = tid & 15;
    float C[4][4];
#pragma unroll
    for (int i = 0; i < 4; i++)
#pragma unroll
        for (int j = 0; j < 4; j++) C[i][j] = 0.f;
#pragma unroll 8
    for (int k = 0; k < NH; k++) {
        float a[4], b[4];
#pragma unroll
        for (int i = 0; i < 4; i++) a[i] = As2[k][tr + 16 * i];
#pragma unroll
        for (int j = 0; j < 4; j++) b[j] = Bs2[k][tc + 16 * j];
#pragma unroll
        for (int i = 0; i < 4; i++)
#pragma unroll
            for (int j = 0; j < 4; j++) C[i][j] += a[i] * b[j];
    }
#pragma unroll
    for (int i = 0; i < 4; i++) {
        int b = r0 + tr + 16 * i;
#pragma unroll
        for (int j = 0; j < 4; j++) {
            int o = c0 + tc + 16 * j;
            size_t idx = (size_t)b * NA + o;
            out[idx] = (C[i][j] + __ldg(b2f + o)) * __ldg(mask + idx);
        }
    }
}

// ---------------- launch ------------------------------------------------------

extern "C" void kernel_launch(void* const* d_in, const int* in_sizes, int n_in,
                              void* d_out, int out_size) {
    const float* x0 = (const float*)d_in[0];
    const float* x1 = (const float*)d_in[1];
    const float* x2 = (const float*)d_in[2];
    const int* e0 = (const int*)d_in[3];
    const int* e1 = (const int*)d_in[4];
    const int* e2 = (const int*)d_in[5];
    const float* mask = (const float*)d_in[6];
    const float* nw  = (const float*)d_in[7];
    const float* nb  = (const float*)d_in[8];
    const float* nms = (const float*)d_in[9];
    const float* W1  = (const float*)d_in[10];
    const float* b1  = (const float*)d_in[11];
    const float* W2  = (const float*)d_in[12];
    const float* b2  = (const float*)d_in[13];
    const float* wf1 = (const float*)d_in[14];
    const float* bf1 = (const float*)d_in[15];
    const float* wf2 = (const float*)d_in[16];
    const float* bf2 = (const float*)d_in[17];
    float* out = (float*)d_out;

    dim3 gridStats(STATS_BLKS, 3);
    dim3 gridBin(BIN_CTAS, 3);
    dim3 gridCons(BINS, 3);
    dim3 gridN((NN + TB - 1) / TB, 3);

    zeroK<<<(NB * NH + TB - 1) / TB, TB>>>();
    statsK<<<gridStats, TB>>>(x0, x1, x2);
    binK<<<gridBin, TB>>>(e0, e1, e2);
    degC<<<gridCons, TB>>>();
    z1K<<<gridN, TB>>>(x0, x1, x2, nw, nb, nms, W1);
    conv1C<<<gridCons, TB>>>();
    h1z2K<<<gridN, TB>>>(b1, W2);
    conv2C<<<gridCons, TB>>>();
    ff1K<<<dim3(8, 5), TB>>>(b2, wf1);
    ff2K<<<dim3(8, 16), TB>>>(bf1, wf2, bf2, mask, out);
}

// round 11
// speedup vs baseline: 1.1531x; 1.1531x over previous
#include <cuda_runtime.h>
#include <cstdint>

#define NN 512000       // nodes = 512 * 1000
#define NE 8192000      // edges per branch
#define NB 512          // batch
#define NS 1000         // stations
#define NH 64           // ff hidden
#define NA 1024         // actions
#define EPSF 1e-5f

#define TB 256
#define STATS_BLKS 1024
#define EDGE_BLKS 8000          // 8000 * 256 * 4 = NE exactly

// ---------------- scratch ----------------------------------------------------
__device__ float    g_stats[3][16];        // per branch: sum[8], sumsq[8]
__device__ unsigned g_deg[3][NN];          // edge-count per dst (no self loop)
__device__ float4   g_z1[3][NN];           // xw * dinv
__device__ float4   g_acc1[3][NN];         // conv1 accumulator (init = self loop)
__device__ float    g_z2[3][NN];
__device__ float    g_acc2[3][NN];
__device__ float    g_hidden[NB * NH];     // ff1 output

// ---------------- kernels ----------------------------------------------------

__global__ void zeroK() {
    int i = blockIdx.x * blockDim.x + threadIdx.x;
    if (i < 3 * NN) ((unsigned*)g_deg)[i] = 0u;
    if (i < 48)     ((float*)g_stats)[i] = 0.f;
}

// blocks [0,STATS_BLKS) do feature stats, rest do deg histogram. y = branch.
__global__ void statsdegK(const float* __restrict__ x0, const float* __restrict__ x1,
                          const float* __restrict__ x2,
                          const int* __restrict__ e0, const int* __restrict__ e1,
                          const int* __restrict__ e2) {
    int br = blockIdx.y;
    if (blockIdx.x < STATS_BLKS) {
        const float* x = br == 0 ? x0 : (br == 1 ? x1 : x2);
        float s[8], q[8];
#pragma unroll
        for (int i = 0; i < 8; i++) { s[i] = 0.f; q[i] = 0.f; }
        int stride = STATS_BLKS * TB;
        for (int n = blockIdx.x * TB + threadIdx.x; n < NN; n += stride) {
            const float4* p = (const float4*)(x + (size_t)n * 8);
            float4 a = __ldg(p), b = __ldg(p + 1);
            float v[8] = {a.x, a.y, a.z, a.w, b.x, b.y, b.z, b.w};
#pragma unroll
            for (int i = 0; i < 8; i++) { s[i] += v[i]; q[i] += v[i] * v[i]; }
        }
#pragma unroll
        for (int i = 0; i < 8; i++) {
#pragma unroll
            for (int o = 16; o; o >>= 1) {
                s[i] += __shfl_down_sync(0xffffffffu, s[i], o);
                q[i] += __shfl_down_sync(0xffffffffu, q[i], o);
            }
        }
        __shared__ float sh[16];
        if (threadIdx.x < 16) sh[threadIdx.x] = 0.f;
        __syncthreads();
        if ((threadIdx.x & 31) == 0) {
#pragma unroll
            for (int i = 0; i < 8; i++) {
                atomicAdd(&sh[i], s[i]);
                atomicAdd(&sh[8 + i], q[i]);
            }
        }
        __syncthreads();
        if (threadIdx.x < 16) atomicAdd(&g_stats[br][threadIdx.x], sh[threadIdx.x]);
    } else {
        const int* ei = br == 0 ? e0 : (br == 1 ? e1 : e2);
        int base = (blockIdx.x - STATS_BLKS) * 1024 + threadIdx.x * 4;
        int4 d4 = __ldg((const int4*)(ei + NE + base));
        atomicAdd(&g_deg[br][d4.x], 1u);
        atomicAdd(&g_deg[br][d4.y], 1u);
        atomicAdd(&g_deg[br][d4.z], 1u);
        atomicAdd(&g_deg[br][d4.w], 1u);
    }
}

// z1 = (norm(x)@W1)*dinv, GraphNorm affine folded in (thread 0 per block).
__global__ void z1K(const float* __restrict__ x0, const float* __restrict__ x1,
                    const float* __restrict__ x2,
                    const float* __restrict__ nw, const float* __restrict__ nbp,
                    const float* __restrict__ nms, const float* __restrict__ W1) {
    int br = blockIdx.y;
    const float* x = br == 0 ? x0 : (br == 1 ? x1 : x2);
    __shared__ float sA[32];
    __shared__ float sD[4];
    if (threadIdx.x == 0) {
        const float inv = 1.0f / (float)NN;
        float a[8], d[8];
#pragma unroll
        for (int i = 0; i < 8; i++) {
            float mean = g_stats[br][i] * inv;
            float m2   = g_stats[br][8 + i] * inv;
            float c    = mean * nms[i];
            float var  = m2 - 2.f * c * mean + c * c;
            float ai   = nw[i] * rsqrtf(var + EPSF);
            a[i] = ai;
            d[i] = nbp[i] - c * ai;
        }
#pragma unroll
        for (int j = 0; j < 4; j++) {
            float dv = 0.f;
#pragma unroll
            for (int i = 0; i < 8; i++) {
                sA[i * 4 + j] = a[i] * W1[i * 4 + j];
                dv += d[i] * W1[i * 4 + j];
            }
            sD[j] = dv;
        }
    }
    __syncthreads();
    int n = blockIdx.x * TB + threadIdx.x;
    if (n >= NN) return;
    const float4* p = (const float4*)(x + (size_t)n * 8);
    float4 a = __ldg(p), b = __ldg(p + 1);
    float v[8] = {a.x, a.y, a.z, a.w, b.x, b.y, b.z, b.w};
    float dinv = rsqrtf((float)(g_deg[br][n] + 1u));
    float o[4];
#pragma unroll
    for (int j = 0; j < 4; j++) {
        float acc = sD[j];
#pragma unroll
        for (int i = 0; i < 8; i++) acc += v[i] * sA[i * 4 + j];
        o[j] = acc * dinv;
    }
    float4 z = make_float4(o[0], o[1], o[2], o[3]);
    g_z1[br][n]  = z;
    g_acc1[br][n] = z;
}

// conv1 edge scatter, 4 edges/thread: acc1[dst] += z1[src]
__global__ void scat1K(const int* __restrict__ e0, const int* __restrict__ e1,
                       const int* __restrict__ e2) {
    int br = blockIdx.y;
    const int* ei = br == 0 ? e0 : (br == 1 ? e1 : e2);
    int base = blockIdx.x * 1024 + threadIdx.x * 4;
    int4 s4 = __ldg((const int4*)(ei + base));
    int4 d4 = __ldg((const int4*)(ei + NE + base));
    float4 z0 = __ldg(&g_z1[br][s4.x]);
    float4 z1 = __ldg(&g_z1[br][s4.y]);
    float4 z2 = __ldg(&g_z1[br][s4.z]);
    float4 z3 = __ldg(&g_z1[br][s4.w]);
    atomicAdd(&g_acc1[br][d4.x], z0);
    atomicAdd(&g_acc1[br][d4.y], z1);
    atomicAdd(&g_acc1[br][d4.z], z2);
    atomicAdd(&g_acc1[br][d4.w], z3);
}

// h1 = relu(dinv*acc1 + b1); z2 = (h1 . w2) * dinv; acc2 init = z2
__global__ void h1z2K(const float* __restrict__ b1, const float* __restrict__ w2) {
    int br = blockIdx.y;
    int n = blockIdx.x * TB + threadIdx.x;
    if (n >= NN) return;
    float dinv = rsqrtf((float)(g_deg[br][n] + 1u));
    float4 acc = g_acc1[br][n];
    float h0 = fmaxf(fmaf(dinv, acc.x, b1[0]), 0.f);
    float h1 = fmaxf(fmaf(dinv, acc.y, b1[1]), 0.f);
    float h2 = fmaxf(fmaf(dinv, acc.z, b1[2]), 0.f);
    float h3 = fmaxf(fmaf(dinv, acc.w, b1[3]), 0.f);
    float z2 = (h0 * w2[0] + h1 * w2[1] + h2 * w2[2] + h3 * w2[3]) * dinv;
    g_z2[br][n]  = z2;
    g_acc2[br][n] = z2;
}

// conv2 edge scatter, 4 edges/thread: acc2[dst] += z2[src]
__global__ void scat2K(const int* __restrict__ e0, const int* __restrict__ e1,
                       const int* __restrict__ e2) {
    int br = blockIdx.y;
    const int* ei = br == 0 ? e0 : (br == 1 ? e1 : e2);
    int base = blockIdx.x * 1024 + threadIdx.x * 4;
    int4 s4 = __ldg((const int4*)(ei + base));
    int4 d4 = __ldg((const int4*)(ei + NE + base));
    float v0 = __ldg(&g_z2[br][s4.x]);
    float v1 = __ldg(&g_z2[br][s4.y]);
    float v2 = __ldg(&g_z2[br][s4.z]);
    float v3 = __ldg(&g_z2[br][s4.w]);
    atomicAdd(&g_acc2[br][d4.x], v0);
    atomicAdd(&g_acc2[br][d4.y], v1);
    atomicAdd(&g_acc2[br][d4.z], v2);
    atomicAdd(&g_acc2[br][d4.w], v3);
}

// ff1, 2 batch rows per block (grid NB/2): concat rows in smem (conv2 epilogue
// fused), shared w-stream amortized over both rows.
__global__ void ff1K(const float* __restrict__ b2, const float* __restrict__ w,
                     const float* __restrict__ bias) {
    __shared__ float row[2 * 3 * NS];      // 24000 B
    __shared__ float part[8][NH];          // [r*4+g][j]
    int b0 = blockIdx.x * 2;
    float b2v = __ldg(b2);
    int tid = threadIdx.x;
    for (int e = tid; e < 2 * 3 * NS; e += TB) {
        int r  = e / (3 * NS);
        int kk = e - r * (3 * NS);
        int br = kk / NS;
        int s  = kk - br * NS;
        int n  = (b0 + r) * NS + s;
        float dinv = rsqrtf((float)(g_deg[br][n] + 1u));
        row[e] = fmaxf(fmaf(dinv, g_acc2[br][n], b2v), 0.f);
    }
    __syncthreads();
    int g = tid >> 6;                       // k-quarter 0..3
    int j = tid & 63;                       // hidden col
    float a0 = 0.f, a1 = 0.f;
    int k0 = g * 750, k1 = k0 + 750;
    for (int k = k0; k < k1; ++k) {
        float wv = __ldg(w + (size_t)k * NH + j);
        a0 = fmaf(row[k], wv, a0);
        a1 = fmaf(row[3 * NS + k], wv, a1);
    }
    part[g][j]     = a0;
    part[4 + g][j] = a1;
    __syncthreads();
    if (tid < 2 * NH) {
        int r = tid >> 6;
        int c = tid & 63;
        float v = part[r * 4 + 0][c] + part[r * 4 + 1][c] +
                  part[r * 4 + 2][c] + part[r * 4 + 3][c] + bias[c];
        g_hidden[(b0 + r) * NH + c] = fmaxf(v, 0.f);
    }
}

// ff2, 2 batch rows per block: out = hidden @ w2f + b2f, * mask
__global__ void ff2K(const float* __restrict__ w, const float* __restrict__ bias,
                     const float* __restrict__ mask, float* __restrict__ out) {
    __shared__ float h[2 * NH];
    int b0 = blockIdx.x * 2;
    int tid = threadIdx.x;
    if (tid < 2 * NH) h[tid] = g_hidden[b0 * NH + tid];
    __syncthreads();
    for (int o = tid; o < NA; o += TB) {
        float a0 = bias[o], a1 = a0;
#pragma unroll 8
        for (int k = 0; k < NH; k++) {
            float wv = __ldg(w + (size_t)k * NA + o);
            a0 = fmaf(h[k], wv, a0);
            a1 = fmaf(h[NH + k], wv, a1);
        }
        size_t i0 = (size_t)b0 * NA + o;
        size_t i1 = i0 + NA;
        out[i0] = a0 * mask[i0];
        out[i1] = a1 * mask[i1];
    }
}

// ---------------- launch ------------------------------------------------------

extern "C" void kernel_launch(void* const* d_in, const int* in_sizes, int n_in,
                              void* d_out, int out_size) {
    const float* x0 = (const float*)d_in[0];
    const float* x1 = (const float*)d_in[1];
    const float* x2 = (const float*)d_in[2];
    const int* e0 = (const int*)d_in[3];
    const int* e1 = (const int*)d_in[4];
    const int* e2 = (const int*)d_in[5];
    const float* mask = (const float*)d_in[6];
    const float* nw  = (const float*)d_in[7];
    const float* nb  = (const float*)d_in[8];
    const float* nms = (const float*)d_in[9];
    const float* W1  = (const float*)d_in[10];
    const float* b1  = (const float*)d_in[11];
    const float* W2  = (const float*)d_in[12];
    const float* b2  = (const float*)d_in[13];
    const float* wf1 = (const float*)d_in[14];
    const float* bf1 = (const float*)d_in[15];
    const float* wf2 = (const float*)d_in[16];
    const float* bf2 = (const float*)d_in[17];
    float* out = (float*)d_out;

    dim3 gridSD(STATS_BLKS + EDGE_BLKS, 3);
    dim3 gridE(EDGE_BLKS, 3);
    dim3 gridN((NN + TB - 1) / TB, 3);

    zeroK<<<(3 * NN + TB - 1) / TB, TB>>>();
    statsdegK<<<gridSD, TB>>>(x0, x1, x2, e0, e1, e2);
    z1K<<<gridN, TB>>>(x0, x1, x2, nw, nb, nms, W1);
    scat1K<<<gridE, TB>>>(e0, e1, e2);
    h1z2K<<<gridN, TB>>>(b1, W2);
    scat2K<<<gridE, TB>>>(e0, e1, e2);
    ff1K<<<NB / 2, TB>>>(b2, wf1, bf1);
    ff2K<<<NB / 2, TB>>>(wf2, bf2, mask, out);
}